// round 14
// baseline (speedup 1.0000x reference)
#include <cuda_runtime.h>
#include <math.h>

#define TT 1000
#define BB 256
#define II 128
#define NN 512
#define BN (BB * NN)
#define ALPHA_C 0.2f

#define GROUPS 8      // batch groups of 32 rows
#define SLICES 16     // N slices of 32 cols
#define NWARP 32      // warps per CTA
#define KCH 16        // K elements per warp

#define S_BUF 20      // per-warp h buffer row stride (floats); 80B = 16B-aligned
#define BUF_FLOATS (32 * S_BUF)                 // 640 floats per warp
#define HS_FLOATS (NWARP * BUF_FLOATS)          // 20480 floats = 81920 B
#define RED_FLOATS (NWARP * 32 * 32)            // 32 chunks x 32 rows x 32 cols
#define SMEM_BYTES ((HS_FLOATS + RED_FLOATS) * 4)    // 212992 B

// Per-group monotonic arrival counters; reset by xproj kernel each replay.
__device__ unsigned int g_bar[GROUPS];

typedef unsigned long long u64;

__device__ __forceinline__ u64 pk2(float x, float y) {
    u64 r; asm("mov.b64 %0, {%1, %2};" : "=l"(r) : "f"(x), "f"(y)); return r;
}
__device__ __forceinline__ float2 upk(u64 v) {
    float2 f; asm("mov.b64 {%0, %1}, %2;" : "=f"(f.x), "=f"(f.y) : "l"(v)); return f;
}
__device__ __forceinline__ u64 fma2(u64 a, u64 b, u64 c) {
    u64 r; asm("fma.rn.f32x2 %0, %1, %2, %3;" : "=l"(r) : "l"(a), "l"(b), "l"(c)); return r;
}

// ---------------------------------------------------------------------------
// Kernel A: xproj[m, n] = sum_i x[m, i] * W_in[n, i] + b_in[n]
// Written straight into out[t] slots. Packed f32x2 FMA. Also resets g_bar.
// ---------------------------------------------------------------------------
__global__ __launch_bounds__(256) void xproj_kernel(
    const float* __restrict__ X, const float* __restrict__ Win,
    const float* __restrict__ bin, float* __restrict__ C)
{
    if (blockIdx.x == 0 && blockIdx.y == 0 && threadIdx.x < GROUPS)
        g_bar[threadIdx.x] = 0;

    __shared__ float As[16 * 64];
    __shared__ float Bs[16 * 64];

    const int mBase = blockIdx.y * 64;
    const int nBase = blockIdx.x * 64;
    const int tid = threadIdx.x;
    const int lrow = tid >> 2;           // 0..63
    const int lcol = (tid & 3) << 2;     // 0,4,8,12
    const float* Ap = X + (size_t)(mBase + lrow) * II + lcol;
    const float* Bp = Win + (size_t)(nBase + lrow) * II + lcol;

    const int trow = (tid >> 4) << 2;    // m offset within tile
    const int tcol = (tid & 15) << 2;    // n offset within tile

    u64 acc[4][2];
    #pragma unroll
    for (int i = 0; i < 4; i++) { acc[i][0] = 0; acc[i][1] = 0; }

    for (int k0 = 0; k0 < II; k0 += 16) {
        float4 a4 = *(const float4*)(Ap + k0);
        float4 b4 = *(const float4*)(Bp + k0);
        As[(lcol + 0) * 64 + lrow] = a4.x;
        As[(lcol + 1) * 64 + lrow] = a4.y;
        As[(lcol + 2) * 64 + lrow] = a4.z;
        As[(lcol + 3) * 64 + lrow] = a4.w;
        Bs[(lcol + 0) * 64 + lrow] = b4.x;
        Bs[(lcol + 1) * 64 + lrow] = b4.y;
        Bs[(lcol + 2) * 64 + lrow] = b4.z;
        Bs[(lcol + 3) * 64 + lrow] = b4.w;
        __syncthreads();
        #pragma unroll
        for (int kk = 0; kk < 16; kk++) {
            float4 ra4 = *(const float4*)&As[kk * 64 + trow];
            ulonglong2 rb = *(const ulonglong2*)&Bs[kk * 64 + tcol];
            float ra[4] = {ra4.x, ra4.y, ra4.z, ra4.w};
            #pragma unroll
            for (int i = 0; i < 4; i++) {
                u64 d = pk2(ra[i], ra[i]);
                acc[i][0] = fma2(d, rb.x, acc[i][0]);
                acc[i][1] = fma2(d, rb.y, acc[i][1]);
            }
        }
        __syncthreads();
    }

    float4 bv = *(const float4*)&bin[nBase + tcol];
    #pragma unroll
    for (int i = 0; i < 4; i++) {
        float2 p0 = upk(acc[i][0]);
        float2 p1 = upk(acc[i][1]);
        float4 o;
        o.x = p0.x + bv.x;
        o.y = p0.y + bv.y;
        o.z = p1.x + bv.z;
        o.w = p1.y + bv.w;
        *(float4*)&C[(size_t)(mBase + trow + i) * NN + nBase + tcol] = o;
    }
}

// ---------------------------------------------------------------------------
// Persistent recurrence kernel. 128 CTAs = 8 batch-groups x 16 N-slices.
// CTA tile: 32 batch rows x 32 N cols, 1024 threads (32 warps, 8/SMSP).
//   - Warp w: K-chunk [16w, 16w+16), lane = column. W as 8 packed-u64 regs.
//   - Warp-private staging of its 32-row x 16-k h slice; __syncwarp only.
//   - GEMM: broadcast LDS.128 + 2 FMA2 per (row, 4k); rows in 4 passes of 8
//     (8 independent u64 acc chains, 16 regs) to hold the 64-reg budget.
//   - K reduction across 32 chunks: warp w reduces row w (1 output/thread,
//     conflict-free scalar LDS, 4 parallel FADD chains).
//   - xp prefetched at loop top; barrier = bar + tid0 fence/atomic/acquire.
// ---------------------------------------------------------------------------
__global__ __launch_bounds__(1024, 1) void rnn_persistent(
    const float* __restrict__ h0, const float* __restrict__ Whh,
    float* __restrict__ out)
{
    extern __shared__ float sm[];
    float* red = sm + HS_FLOATS;            // [32 chunks][32 rows][32 cols]

    const int cta = blockIdx.x;
    const int bg = cta >> 4;            // batch group 0..7
    const int ns = cta & 15;            // N slice 0..15
    const int bBase = bg * 32;
    const int nBase = ns * 32;
    const int tid = threadIdx.x;        // 0..1023
    const int wid = tid >> 5;           // warp 0..31 -> K-chunk
    const int lane = tid & 31;          // = column within slice

    float* buf = sm + wid * BUF_FLOATS;     // this warp's h slice [32][S_BUF]

    // --- one-time W load: Wp[j] = packed k-pair j of W[nBase+lane][16w..16w+15]
    u64 Wp[8];
    {
        const float* wp = Whh + (size_t)(nBase + lane) * NN + wid * KCH;
        #pragma unroll
        for (int i = 0; i < 4; i++) {
            ulonglong2 v = __ldg((const ulonglong2*)(wp + i * 4));
            Wp[2 * i + 0] = v.x;
            Wp[2 * i + 1] = v.y;
        }
    }

    // staging mapping (within warp): rows lane>>2 + {0,8,16,24}, phase lane&3
    const int sa = lane >> 2;           // 0..7 row sub-index
    const int sp = lane & 3;            // float4 phase within 16-float slice

    // reduce/epilogue mapping: row = wid, col = lane (1 output per thread)
    const int er = wid;
    const int ec = lane;

    for (int t = 0; t < TT; t++) {
        // --- prefetch xproj for epilogue (hidden under staging + GEMM)
        float xp = __ldcg(out + (size_t)t * BN + (size_t)(bBase + er) * NN + nBase + ec);

        // --- warp-private staging of h_{t-1} k-slice [32 rows][16 k]
        {
            const float* src = ((t == 0) ? (h0 + (size_t)bBase * NN)
                                         : (out + (size_t)(t - 1) * BN + (size_t)bBase * NN))
                               + wid * KCH + sp * 4;
            #pragma unroll
            for (int i = 0; i < 4; i++) {
                const int row = i * 8 + sa;
                float4 v = __ldcg((const float4*)(src + (size_t)row * NN));
                *(float4*)(buf + row * S_BUF + sp * 4) = v;
            }
        }
        __syncwarp();

        // --- GEMM over this warp's K-chunk, rows in 4 passes of 8
        #pragma unroll
        for (int pass = 0; pass < 4; pass++) {
            u64 acc[8];
            #pragma unroll
            for (int r = 0; r < 8; r++) acc[r] = 0;

            #pragma unroll
            for (int j = 0; j < 4; j++) {           // 4 k's per j
                #pragma unroll
                for (int r = 0; r < 8; r++) {
                    ulonglong2 hv = *(const ulonglong2*)(buf + (pass * 8 + r) * S_BUF + 4 * j);
                    acc[r] = fma2(hv.x, Wp[2 * j + 0], acc[r]);
                    acc[r] = fma2(hv.y, Wp[2 * j + 1], acc[r]);
                }
            }

            // horizontal add + write partials: red[wid][row][lane]
            #pragma unroll
            for (int r = 0; r < 8; r++) {
                float2 p = upk(acc[r]);
                red[(wid * 32 + pass * 8 + r) * 32 + lane] = p.x + p.y;
            }
        }
        __syncthreads();

        // --- reduce 32 K-chunks for output (row er, col ec); 4 parallel chains
        float s0 = 0.f, s1 = 0.f, s2 = 0.f, s3 = 0.f;
        #pragma unroll
        for (int c = 0; c < 32; c += 4) {
            s0 += red[((c + 0) * 32 + er) * 32 + ec];
            s1 += red[((c + 1) * 32 + er) * 32 + ec];
            s2 += red[((c + 2) * 32 + er) * 32 + ec];
            s3 += red[((c + 3) * 32 + er) * 32 + ec];
        }
        float p = (s0 + s1) + (s2 + s3);

        // hprev: k index = nBase+ec lives in chunk (nBase+ec)/16's buffer
        const int hc = (nBase + ec) >> 4;       // owning warp/chunk
        float hp = sm[hc * BUF_FLOATS + er * S_BUF + ((nBase + ec) & 15)];

        float o = hp * (1.0f - ALPHA_C) + ALPHA_C * tanhf(xp + p);

        float* dst = out + (size_t)t * BN + (size_t)(bBase + er) * NN + nBase + ec;
        __stcg(dst, o);
        if (t == TT - 1) {  // final hidden state appended after the sequence
            __stcg(out + (size_t)TT * BN + (size_t)(bBase + er) * NN + nBase + ec, o);
        }

        // --- group barrier (16 CTAs sharing these batch rows), monotonic.
        __syncthreads();
        if (t < TT - 1) {
            if (tid == 0) {
                asm volatile("fence.acq_rel.gpu;" ::: "memory");
                atomicAdd(&g_bar[bg], 1u);
                const unsigned target = 16u * (unsigned)(t + 1);
                unsigned v;
                while (true) {
                    asm volatile("ld.acquire.gpu.global.u32 %0, [%1];"
                                 : "=r"(v) : "l"(&g_bar[bg]) : "memory");
                    if (v >= target) break;
                    __nanosleep(32);
                }
            }
            __syncthreads();
        }
    }
}

extern "C" void kernel_launch(void* const* d_in, const int* in_sizes, int n_in,
                              void* d_out, int out_size)
{
    (void)in_sizes; (void)n_in; (void)out_size;
    const float* x   = (const float*)d_in[0];   // [1000, 256, 128]
    const float* h0  = (const float*)d_in[1];   // [256, 512]
    const float* Win = (const float*)d_in[2];   // [512, 128]
    const float* bin = (const float*)d_in[3];   // [512]
    const float* Whh = (const float*)d_in[4];   // [512, 512]
    float* out = (float*)d_out;                 // [1000*256*512 + 256*512]

    static int smem_set = 0;
    if (!smem_set) {
        cudaFuncSetAttribute(rnn_persistent,
                             cudaFuncAttributeMaxDynamicSharedMemorySize, SMEM_BYTES);
        smem_set = 1;
    }

    // Phase 1: xproj for all timesteps -> out[t] slots (also resets g_bar).
    dim3 gA(NN / 64, (TT * BB) / 64);           // (8, 4000)
    xproj_kernel<<<gA, 256>>>(x, Win, bin, out);

    // Phase 2: persistent recurrence, 128 co-resident CTAs.
    rnn_persistent<<<GROUPS * SLICES, 1024, SMEM_BYTES>>>(h0, Whh, out);
}